// round 2
// baseline (speedup 1.0000x reference)
#include <cuda_runtime.h>
#include <cstdint>
#include <cstddef>

#define BB 256
#define TT 2048
#define DD0 57
#define HH 16
#define GG 64
#define NPOS (BB*TT)          // 524288
#define NGATE ((size_t)NPOS*GG) // 33554432

// ---------------- scratch (device globals, no allocation) ----------------
__device__ float g_xg[NGATE];                    // gate preactivations, layout [pos][j][4] (i,f,g,o per unit)
__device__ float g_ha[(size_t)NPOS * HH];        // h ping
__device__ float g_hb[(size_t)NPOS * HH];        // h pong
__device__ float g_stats[32];                    // [0:16) sum, [16:32) sumsq
__device__ float g_coef[68];                     // [0:64) w'[o][j], [64:68) b'[o]

// ---------------- fast activations (accurate: ex2+rcp, ~1e-6 rel) --------
__device__ __forceinline__ float f_sigm(float x) {
    float e, r;
    asm("ex2.approx.f32 %0, %1;" : "=f"(e) : "f"(-1.4426950408889634f * x));
    asm("rcp.approx.f32 %0, %1;" : "=f"(r) : "f"(1.0f + e));
    return r;
}
__device__ __forceinline__ float f_tanh(float x) {
    // tanh(x) = 2*sigmoid(2x) - 1
    float e, r;
    asm("ex2.approx.f32 %0, %1;" : "=f"(e) : "f"(-2.8853900817779268f * x));
    asm("rcp.approx.f32 %0, %1;" : "=f"(r) : "f"(1.0f + e));
    return fmaf(2.0f, r, -1.0f);
}

// ---------------- input projection: xg[pos][g] = b + in[pos,:] @ W[g,:] ---
// output layout interleaved per unit: idx = (pos*16 + (g&15))*4 + (g>>4)
template<int DIN>
__global__ void proj_kernel(const float* __restrict__ in,
                            const float* __restrict__ W,
                            const float* __restrict__ bih,
                            const float* __restrict__ bhh,
                            float* __restrict__ xg)
{
    int gid = blockIdx.x * blockDim.x + threadIdx.x;
    int r   = gid & 63;
    int pos = gid >> 6;
    const float* xr = in + (size_t)pos * DIN;
    const float* wr = W  + (size_t)r   * DIN;
    float acc = bih[r] + bhh[r];
#pragma unroll
    for (int d = 0; d < DIN; ++d)
        acc = fmaf(__ldg(xr + d), __ldg(wr + d), acc);
    xg[((size_t)pos * 16 + (r & 15)) * 4 + (r >> 4)] = acc;
}

// ---------------- recurrent scan: 16 lanes per batch, 2 batches/warp ------
__global__ void __launch_bounds__(32)
scan_kernel(const float4* __restrict__ xg,
            const float*  __restrict__ Whh,   // [64,16]
            float*        __restrict__ hout,  // [B,T,16]
            const int*    __restrict__ lengths,
            int apply_mask)
{
    const int lane = threadIdx.x;
    const int j    = lane & 15;
    const int b    = blockIdx.x * 2 + (lane >> 4);

    // per-unit recurrent weights in registers: rows j (i), 16+j (f), 32+j (g), 48+j (o)
    float wi[16], wf[16], wg[16], wo[16];
#pragma unroll
    for (int k = 0; k < 16; ++k) {
        wi[k] = __ldg(Whh + ( 0 + j) * 16 + k);
        wf[k] = __ldg(Whh + (16 + j) * 16 + k);
        wg[k] = __ldg(Whh + (32 + j) * 16 + k);
        wo[k] = __ldg(Whh + (48 + j) * 16 + k);
    }
    const int len = apply_mask ? lengths[b] : TT;

    const float4* xp = xg   + (size_t)b * TT * 16 + j;   // stride 16 float4 per t
    float*        hp = hout + (size_t)b * TT * 16 + j;

    float c = 0.0f, h = 0.0f;
    float4 pre = xp[0];
    for (int t = 0; t < TT; ++t) {
        float4 cur = pre;
        int tn = (t + 1 < TT) ? (t + 1) : t;
        pre = xp[(size_t)tn * 16];                        // prefetch next step

        float a_i = cur.x, a_f = cur.y, a_g = cur.z, a_o = cur.w;
#pragma unroll
        for (int k = 0; k < 16; ++k) {
            float hk = __shfl_sync(0xffffffffu, h, k, 16);
            a_i = fmaf(hk, wi[k], a_i);
            a_f = fmaf(hk, wf[k], a_f);
            a_g = fmaf(hk, wg[k], a_g);
            a_o = fmaf(hk, wo[k], a_o);
        }
        float gi = f_sigm(a_i);
        float gf = f_sigm(a_f);
        float gg = f_tanh(a_g);
        float go = f_sigm(a_o);
        c = fmaf(gf, c, gi * gg);
        h = go * f_tanh(c);

        hp[(size_t)t * 16] = (t < len) ? h : 0.0f;
    }
}

// ---------------- BN stats --------------------------------------------------
__global__ void zero_stats_kernel() {
    if (threadIdx.x < 32) g_stats[threadIdx.x] = 0.0f;
}

__global__ void stats_kernel(const float* __restrict__ h2)
{
    __shared__ float ss[16], sq[16];
    int tid = threadIdx.x;
    if (tid < 16) { ss[tid] = 0.0f; sq[tid] = 0.0f; }
    __syncthreads();
    int j = tid & 15;
    int rpb = blockDim.x >> 4;  // positions covered per block per pass
    float s = 0.0f, s2 = 0.0f;
    for (int pos = blockIdx.x * rpb + (tid >> 4); pos < NPOS; pos += gridDim.x * rpb) {
        float v = h2[(size_t)pos * 16 + j];
        s += v; s2 += v * v;
    }
    atomicAdd(&ss[j], s);
    atomicAdd(&sq[j], s2);
    __syncthreads();
    if (tid < 16) {
        atomicAdd(&g_stats[tid],      ss[tid]);
        atomicAdd(&g_stats[16 + tid], sq[tid]);
    }
}

// ---------------- fold BN into FC ------------------------------------------
__global__ void coef_kernel(const float* __restrict__ gamma,
                            const float* __restrict__ beta,
                            const float* __restrict__ fcw,
                            const float* __restrict__ fcb)
{
    __shared__ float scl[16], sht[16];
    int tid = threadIdx.x;
    if (tid < 16) {
        const float inv_n = 1.0f / (float)NPOS;
        float mean = g_stats[tid] * inv_n;
        float var  = g_stats[16 + tid] * inv_n - mean * mean;
        float s = rsqrtf(var + 1e-5f) * gamma[tid];
        scl[tid] = s;
        sht[tid] = beta[tid] - mean * s;
    }
    __syncthreads();
    if (tid < 64) {
        int o = tid >> 4, j = tid & 15;
        g_coef[tid] = fcw[o * 16 + j] * scl[j];
    }
    if (tid < 4) {
        float bb = fcb[tid];
        for (int j = 0; j < 16; ++j)
            bb += fcw[tid * 16 + j] * sht[j];
        g_coef[64 + tid] = bb;
    }
}

// ---------------- final GEMV: out[pos][o] = b'[o] + h[pos,:] @ w'[o,:] -----
__global__ void out_kernel(const float* __restrict__ h2, float* __restrict__ out)
{
    int pos = blockIdx.x * blockDim.x + threadIdx.x;
    if (pos >= NPOS) return;
    const float4* hp = (const float4*)(h2 + (size_t)pos * 16);
    float4 v0 = hp[0], v1 = hp[1], v2 = hp[2], v3 = hp[3];
    float hv[16] = { v0.x, v0.y, v0.z, v0.w, v1.x, v1.y, v1.z, v1.w,
                     v2.x, v2.y, v2.z, v2.w, v3.x, v3.y, v3.z, v3.w };
    float o0 = g_coef[64], o1 = g_coef[65], o2 = g_coef[66], o3 = g_coef[67];
#pragma unroll
    for (int jj = 0; jj < 16; ++jj) {
        float hvv = hv[jj];
        o0 = fmaf(hvv, g_coef[ 0 + jj], o0);
        o1 = fmaf(hvv, g_coef[16 + jj], o1);
        o2 = fmaf(hvv, g_coef[32 + jj], o2);
        o3 = fmaf(hvv, g_coef[48 + jj], o3);
    }
    float4 r = { o0, o1, o2, o3 };
    ((float4*)out)[pos] = r;
}

// ---------------- host ------------------------------------------------------
extern "C" void kernel_launch(void* const* d_in, const int* in_sizes, int n_in,
                              void* d_out, int out_size)
{
    const float* x    = (const float*)d_in[0];
    const int*   len  = (const int*)  d_in[1];
    const float* Wih0 = (const float*)d_in[2];
    const float* Whh0 = (const float*)d_in[3];
    const float* bih0 = (const float*)d_in[4];
    const float* bhh0 = (const float*)d_in[5];
    const float* Wih1 = (const float*)d_in[6];
    const float* Whh1 = (const float*)d_in[7];
    const float* bih1 = (const float*)d_in[8];
    const float* bhh1 = (const float*)d_in[9];
    const float* Wih2 = (const float*)d_in[10];
    const float* Whh2 = (const float*)d_in[11];
    const float* bih2 = (const float*)d_in[12];
    const float* bhh2 = (const float*)d_in[13];
    const float* gam  = (const float*)d_in[14];
    const float* bet  = (const float*)d_in[15];
    const float* fcw  = (const float*)d_in[16];
    const float* fcb  = (const float*)d_in[17];

    float *xg, *ha, *hb;
    cudaGetSymbolAddress((void**)&xg, g_xg);
    cudaGetSymbolAddress((void**)&ha, g_ha);
    cudaGetSymbolAddress((void**)&hb, g_hb);

    const int PROJ_BLK = 256;
    const int proj_grid = (int)(NGATE / PROJ_BLK);   // 131072

    // layer 0
    proj_kernel<DD0><<<proj_grid, PROJ_BLK>>>(x, Wih0, bih0, bhh0, xg);
    scan_kernel<<<BB / 2, 32>>>((const float4*)xg, Whh0, ha, len, 0);
    // layer 1
    proj_kernel<HH><<<proj_grid, PROJ_BLK>>>(ha, Wih1, bih1, bhh1, xg);
    scan_kernel<<<BB / 2, 32>>>((const float4*)xg, Whh1, hb, len, 0);
    // layer 2 (mask applied at store)
    proj_kernel<HH><<<proj_grid, PROJ_BLK>>>(hb, Wih2, bih2, bhh2, xg);
    scan_kernel<<<BB / 2, 32>>>((const float4*)xg, Whh2, ha, len, 1);

    // BN stats + fold into FC + output
    zero_stats_kernel<<<1, 32>>>();
    stats_kernel<<<1024, 256>>>(ha);
    coef_kernel<<<1, 64>>>(gam, bet, fcw, fcb);
    out_kernel<<<NPOS / 256, 256>>>(ha, (float*)d_out);
}

// round 3
// speedup vs baseline: 4.4348x; 4.4348x over previous
#include <cuda_runtime.h>
#include <cstdint>
#include <cstddef>

#define BB 256
#define TT 2048
#define DD0 57
#define HH 16
#define GG 64
#define NPOS (BB*TT)            // 524288
#define NGATE ((size_t)NPOS*GG) // 33554432

typedef unsigned long long u64;

// ---------------- scratch (device globals, no allocation) ----------------
__device__ float g_xg[NGATE];                    // gate preacts, layout [pos][unit][4] (i,f,g,o)
__device__ float g_ha[(size_t)NPOS * HH];        // h ping
__device__ float g_hb[(size_t)NPOS * HH];        // h pong
__device__ float g_stats[32];                    // [0:16) sum, [16:32) sumsq
__device__ float g_coef[68];                     // [0:64) w'[o][j], [64:68) b'[o]

// ---------------- f32x2 packed helpers ------------------------------------
__device__ __forceinline__ u64 pk2(float lo, float hi) {
    u64 r; asm("mov.b64 %0,{%1,%2};" : "=l"(r) : "f"(lo), "f"(hi)); return r;
}
__device__ __forceinline__ void upk2(float& lo, float& hi, u64 v) {
    asm("mov.b64 {%0,%1},%2;" : "=f"(lo), "=f"(hi) : "l"(v));
}
__device__ __forceinline__ u64 fma2(u64 a, u64 b, u64 c) {
    u64 r; asm("fma.rn.f32x2 %0,%1,%2,%3;" : "=l"(r) : "l"(a), "l"(b), "l"(c)); return r;
}
__device__ __forceinline__ u64 add2(u64 a, u64 b) {
    u64 r; asm("add.rn.f32x2 %0,%1,%2;" : "=l"(r) : "l"(a), "l"(b)); return r;
}

// ---------------- fast activations (accurate: ex2+rcp, ~1e-6 rel) --------
__device__ __forceinline__ float f_sigm(float x) {
    float e, r;
    asm("ex2.approx.f32 %0, %1;" : "=f"(e) : "f"(-1.4426950408889634f * x));
    asm("rcp.approx.f32 %0, %1;" : "=f"(r) : "f"(1.0f + e));
    return r;
}
__device__ __forceinline__ float f_tanh(float x) {
    float e, r;
    asm("ex2.approx.f32 %0, %1;" : "=f"(e) : "f"(-2.8853900817779268f * x));
    asm("rcp.approx.f32 %0, %1;" : "=f"(r) : "f"(1.0f + e));
    return fmaf(2.0f, r, -1.0f);
}

// ---------------- input projection ---------------------------------------
// out layout: xg[pos*64 + (r&15)*4 + (r>>4)]
// Block: 256 threads = 64 gate-rows x 4 position slots; PPB positions/block.
// x and W staged in smem; W row held in registers per thread.
template<int DIN, int PPB>
__global__ void __launch_bounds__(256)
proj_kernel(const float* __restrict__ in,
            const float* __restrict__ W,
            const float* __restrict__ bih,
            const float* __restrict__ bhh,
            float* __restrict__ xg)
{
    constexpr int DPAD = (DIN % 2 == 0) ? (DIN + 1) : DIN;   // odd stride: conflict-free
    constexpr int XPAD = DIN;                                 // x row stride
    __shared__ __align__(16) float sx[PPB * XPAD];
    __shared__ float sw[64 * DPAD];

    const int tid = threadIdx.x;
    const int r   = tid & 63;
    const int posBase = blockIdx.x * PPB;

    // stage x coalesced
    for (int i = tid; i < PPB * DIN; i += 256)
        sx[i] = in[(size_t)posBase * DIN + i];
    // stage W coalesced into padded smem
    for (int i = tid; i < 64 * DIN; i += 256)
        sw[(i / DIN) * DPAD + (i % DIN)] = W[i];
    __syncthreads();

    // W row -> registers (conflict-free LDS: odd stride)
    float w[DIN];
#pragma unroll
    for (int d = 0; d < DIN; ++d) w[d] = sw[r * DPAD + d];
    const float bias = __ldg(bih + r) + __ldg(bhh + r);
    const int outIdx = ((r & 15) << 2) | (r >> 4);

    for (int p = (tid >> 6); p < PPB; p += 4) {
        const float* xp = &sx[p * XPAD];
        float acc = bias;
        if constexpr (DIN % 4 == 0) {
            // vectorized broadcast loads
#pragma unroll
            for (int d4 = 0; d4 < DIN / 4; ++d4) {
                float4 v = ((const float4*)xp)[d4];
                acc = fmaf(v.x, w[d4 * 4 + 0], acc);
                acc = fmaf(v.y, w[d4 * 4 + 1], acc);
                acc = fmaf(v.z, w[d4 * 4 + 2], acc);
                acc = fmaf(v.w, w[d4 * 4 + 3], acc);
            }
        } else {
#pragma unroll
            for (int d = 0; d < DIN; ++d)
                acc = fmaf(xp[d], w[d], acc);
        }
        xg[((size_t)(posBase + p) << 6) + outIdx] = acc;
    }
}

// ---------------- recurrent scan ------------------------------------------
// 16 lanes per batch, 2 batches/warp. f32x2 packed gate pairs, even/odd split
// accumulator chains, prefetch pipeline depth 4.
__global__ void __launch_bounds__(32)
scan_kernel(const float4* __restrict__ xg,
            const float*  __restrict__ Whh,   // [64,16]
            float*        __restrict__ hout,  // [B,T,16]
            const int*    __restrict__ lengths,
            int apply_mask)
{
    const int lane = threadIdx.x;
    const int j    = lane & 15;
    const int b    = blockIdx.x * 2 + (lane >> 4);

    // packed recurrent weights: wif[k]=(Wi[j][k],Wf[j][k]), wgo[k]=(Wg,Wo)
    u64 wif[16], wgo[16];
#pragma unroll
    for (int k = 0; k < 16; ++k) {
        float wi = __ldg(Whh + ( 0 + j) * 16 + k);
        float wf = __ldg(Whh + (16 + j) * 16 + k);
        float wg = __ldg(Whh + (32 + j) * 16 + k);
        float wo = __ldg(Whh + (48 + j) * 16 + k);
        wif[k] = pk2(wi, wf);
        wgo[k] = pk2(wg, wo);
    }
    const int len = apply_mask ? lengths[b] : TT;

    const float4* xp = xg   + (size_t)b * TT * 16 + j;   // stride 16 float4 per t
    float*        hp = hout + (size_t)b * TT * 16 + j;

    float c = 0.0f, h = 0.0f;

    float4 buf[4];
#pragma unroll
    for (int u = 0; u < 4; ++u) buf[u] = xp[(size_t)u * 16];

    for (int tb = 0; tb < TT; tb += 4) {
        float4 nb[4];
#pragma unroll
        for (int u = 0; u < 4; ++u) {
            int tn = tb + 4 + u; if (tn > TT - 1) tn = TT - 1;
            nb[u] = xp[(size_t)tn * 16];
        }
#pragma unroll
        for (int u = 0; u < 4; ++u) {
            const int t = tb + u;
            const float4 cur = buf[u];
            u64 aif0 = pk2(cur.x, cur.y), aif1 = 0ull;
            u64 ago0 = pk2(cur.z, cur.w), ago1 = 0ull;
#pragma unroll
            for (int k = 0; k < 16; k += 2) {
                float hk0 = __shfl_sync(0xffffffffu, h, k,     16);
                float hk1 = __shfl_sync(0xffffffffu, h, k + 1, 16);
                u64 h20 = pk2(hk0, hk0);
                u64 h21 = pk2(hk1, hk1);
                aif0 = fma2(h20, wif[k],     aif0);
                ago0 = fma2(h20, wgo[k],     ago0);
                aif1 = fma2(h21, wif[k + 1], aif1);
                ago1 = fma2(h21, wgo[k + 1], ago1);
            }
            u64 aif = add2(aif0, aif1);
            u64 ago = add2(ago0, ago1);
            float a_i, a_f, a_g, a_o;
            upk2(a_i, a_f, aif);
            upk2(a_g, a_o, ago);

            float gi = f_sigm(a_i);
            float gf = f_sigm(a_f);
            float gg = f_tanh(a_g);
            float go = f_sigm(a_o);
            c = fmaf(gf, c, gi * gg);
            h = go * f_tanh(c);

            hp[(size_t)t * 16] = (t < len) ? h : 0.0f;
        }
#pragma unroll
        for (int u = 0; u < 4; ++u) buf[u] = nb[u];
    }
}

// ---------------- BN stats --------------------------------------------------
__global__ void zero_stats_kernel() {
    if (threadIdx.x < 32) g_stats[threadIdx.x] = 0.0f;
}

__global__ void stats_kernel(const float* __restrict__ h2)
{
    __shared__ float ss[16], sq[16];
    int tid = threadIdx.x;
    if (tid < 16) { ss[tid] = 0.0f; sq[tid] = 0.0f; }
    __syncthreads();
    int j = tid & 15;
    int rpb = blockDim.x >> 4;
    float s = 0.0f, s2 = 0.0f;
    for (int pos = blockIdx.x * rpb + (tid >> 4); pos < NPOS; pos += gridDim.x * rpb) {
        float v = h2[(size_t)pos * 16 + j];
        s += v; s2 += v * v;
    }
    atomicAdd(&ss[j], s);
    atomicAdd(&sq[j], s2);
    __syncthreads();
    if (tid < 16) {
        atomicAdd(&g_stats[tid],      ss[tid]);
        atomicAdd(&g_stats[16 + tid], sq[tid]);
    }
}

// ---------------- fold BN into FC ------------------------------------------
__global__ void coef_kernel(const float* __restrict__ gamma,
                            const float* __restrict__ beta,
                            const float* __restrict__ fcw,
                            const float* __restrict__ fcb)
{
    __shared__ float scl[16], sht[16];
    int tid = threadIdx.x;
    if (tid < 16) {
        const float inv_n = 1.0f / (float)NPOS;
        float mean = g_stats[tid] * inv_n;
        float var  = g_stats[16 + tid] * inv_n - mean * mean;
        float s = rsqrtf(var + 1e-5f) * gamma[tid];
        scl[tid] = s;
        sht[tid] = beta[tid] - mean * s;
    }
    __syncthreads();
    if (tid < 64) {
        int o = tid >> 4, jj = tid & 15;
        g_coef[tid] = fcw[o * 16 + jj] * scl[jj];
    }
    if (tid < 4) {
        float bb = fcb[tid];
        for (int jj = 0; jj < 16; ++jj)
            bb += fcw[tid * 16 + jj] * sht[jj];
        g_coef[64 + tid] = bb;
    }
}

// ---------------- final GEMV ------------------------------------------------
__global__ void out_kernel(const float* __restrict__ h2, float* __restrict__ out)
{
    int pos = blockIdx.x * blockDim.x + threadIdx.x;
    if (pos >= NPOS) return;
    const float4* hp = (const float4*)(h2 + (size_t)pos * 16);
    float4 v0 = hp[0], v1 = hp[1], v2 = hp[2], v3 = hp[3];
    float hv[16] = { v0.x, v0.y, v0.z, v0.w, v1.x, v1.y, v1.z, v1.w,
                     v2.x, v2.y, v2.z, v2.w, v3.x, v3.y, v3.z, v3.w };
    float o0 = g_coef[64], o1 = g_coef[65], o2 = g_coef[66], o3 = g_coef[67];
#pragma unroll
    for (int jj = 0; jj < 16; ++jj) {
        float hvv = hv[jj];
        o0 = fmaf(hvv, g_coef[ 0 + jj], o0);
        o1 = fmaf(hvv, g_coef[16 + jj], o1);
        o2 = fmaf(hvv, g_coef[32 + jj], o2);
        o3 = fmaf(hvv, g_coef[48 + jj], o3);
    }
    float4 r = { o0, o1, o2, o3 };
    ((float4*)out)[pos] = r;
}

// ---------------- host ------------------------------------------------------
extern "C" void kernel_launch(void* const* d_in, const int* in_sizes, int n_in,
                              void* d_out, int out_size)
{
    const float* x    = (const float*)d_in[0];
    const int*   len  = (const int*)  d_in[1];
    const float* Wih0 = (const float*)d_in[2];
    const float* Whh0 = (const float*)d_in[3];
    const float* bih0 = (const float*)d_in[4];
    const float* bhh0 = (const float*)d_in[5];
    const float* Wih1 = (const float*)d_in[6];
    const float* Whh1 = (const float*)d_in[7];
    const float* bih1 = (const float*)d_in[8];
    const float* bhh1 = (const float*)d_in[9];
    const float* Wih2 = (const float*)d_in[10];
    const float* Whh2 = (const float*)d_in[11];
    const float* bih2 = (const float*)d_in[12];
    const float* bhh2 = (const float*)d_in[13];
    const float* gam  = (const float*)d_in[14];
    const float* bet  = (const float*)d_in[15];
    const float* fcw  = (const float*)d_in[16];
    const float* fcb  = (const float*)d_in[17];

    float *xg, *ha, *hb;
    cudaGetSymbolAddress((void**)&xg, g_xg);
    cudaGetSymbolAddress((void**)&ha, g_ha);
    cudaGetSymbolAddress((void**)&hb, g_hb);

    constexpr int PPB = 64;
    const int proj_grid = NPOS / PPB;   // 8192

    // layer 0
    proj_kernel<DD0, PPB><<<proj_grid, 256>>>(x, Wih0, bih0, bhh0, xg);
    scan_kernel<<<BB / 2, 32>>>((const float4*)xg, Whh0, ha, len, 0);
    // layer 1
    proj_kernel<HH, PPB><<<proj_grid, 256>>>(ha, Wih1, bih1, bhh1, xg);
    scan_kernel<<<BB / 2, 32>>>((const float4*)xg, Whh1, hb, len, 0);
    // layer 2 (mask applied at store)
    proj_kernel<HH, PPB><<<proj_grid, 256>>>(hb, Wih2, bih2, bhh2, xg);
    scan_kernel<<<BB / 2, 32>>>((const float4*)xg, Whh2, ha, len, 1);

    // BN stats + fold into FC + output
    zero_stats_kernel<<<1, 32>>>();
    stats_kernel<<<1024, 256>>>(ha);
    coef_kernel<<<1, 64>>>(gam, bet, fcw, fcb);
    out_kernel<<<NPOS / 256, 256>>>(ha, (float*)d_out);
}

// round 4
// speedup vs baseline: 5.8073x; 1.3095x over previous
#include <cuda_runtime.h>
#include <cstdint>
#include <cstddef>

#define BB 256
#define TT 2048
#define DD0 57
#define HH 16
#define GG 64
#define NPOS (BB*TT)            // 524288
#define NGATE ((size_t)NPOS*GG) // 33554432

typedef unsigned long long u64;

// ---------------- scratch (device globals, no allocation) ----------------
__device__ float g_xg[NGATE];                    // gate preacts, layout [pos][unit][4] (i,f,g,o)
__device__ float g_ha[(size_t)NPOS * HH];        // h ping
__device__ float g_hb[(size_t)NPOS * HH];        // h pong
__device__ float g_stats[32];                    // [0:16) sum, [16:32) sumsq
__device__ float g_coef[68];                     // [0:64) w'[o][j], [64:68) b'[o]

// ---------------- f32x2 packed helpers ------------------------------------
__device__ __forceinline__ u64 pk2(float lo, float hi) {
    u64 r; asm("mov.b64 %0,{%1,%2};" : "=l"(r) : "f"(lo), "f"(hi)); return r;
}
__device__ __forceinline__ void upk2(float& lo, float& hi, u64 v) {
    asm("mov.b64 {%0,%1},%2;" : "=f"(lo), "=f"(hi) : "l"(v));
}
__device__ __forceinline__ u64 fma2(u64 a, u64 b, u64 c) {
    u64 r; asm("fma.rn.f32x2 %0,%1,%2,%3;" : "=l"(r) : "l"(a), "l"(b), "l"(c)); return r;
}

// ---------------- fast activations (MUFU.TANH) ----------------------------
__device__ __forceinline__ float f_tanh(float x) {
    float r; asm("tanh.approx.f32 %0,%1;" : "=f"(r) : "f"(x)); return r;
}
__device__ __forceinline__ float f_sigm(float x) {
    // sigma(x) = 0.5*tanh(0.5x) + 0.5
    float t = f_tanh(0.5f * x);
    return fmaf(0.5f, t, 0.5f);
}

// ---------------- input projection ---------------------------------------
// out layout: xg[pos*64 + (r&15)*4 + (r>>4)]
template<int DIN, int PPB>
__global__ void __launch_bounds__(256)
proj_kernel(const float* __restrict__ in,
            const float* __restrict__ W,
            const float* __restrict__ bih,
            const float* __restrict__ bhh,
            float* __restrict__ xg)
{
    constexpr int DPAD = (DIN % 2 == 0) ? (DIN + 1) : DIN;   // odd stride: conflict-free
    constexpr int XPAD = DIN;
    __shared__ __align__(16) float sx[PPB * XPAD];
    __shared__ float sw[64 * DPAD];

    const int tid = threadIdx.x;
    const int r   = tid & 63;
    const int posBase = blockIdx.x * PPB;

    for (int i = tid; i < PPB * DIN; i += 256)
        sx[i] = in[(size_t)posBase * DIN + i];
    for (int i = tid; i < 64 * DIN; i += 256)
        sw[(i / DIN) * DPAD + (i % DIN)] = W[i];
    __syncthreads();

    float w[DIN];
#pragma unroll
    for (int d = 0; d < DIN; ++d) w[d] = sw[r * DPAD + d];
    const float bias = __ldg(bih + r) + __ldg(bhh + r);
    const int outIdx = ((r & 15) << 2) | (r >> 4);

    for (int p = (tid >> 6); p < PPB; p += 4) {
        const float* xp = &sx[p * XPAD];
        float acc = bias;
        if constexpr (DIN % 4 == 0) {
#pragma unroll
            for (int d4 = 0; d4 < DIN / 4; ++d4) {
                float4 v = ((const float4*)xp)[d4];
                acc = fmaf(v.x, w[d4 * 4 + 0], acc);
                acc = fmaf(v.y, w[d4 * 4 + 1], acc);
                acc = fmaf(v.z, w[d4 * 4 + 2], acc);
                acc = fmaf(v.w, w[d4 * 4 + 3], acc);
            }
        } else {
#pragma unroll
            for (int d = 0; d < DIN; ++d)
                acc = fmaf(xp[d], w[d], acc);
        }
        xg[((size_t)(posBase + p) << 6) + outIdx] = acc;
    }
}

// ---------------- recurrent scan ------------------------------------------
// 16 lanes per batch, 2 batches/warp. Dot packed along k (h-pairs broadcast
// as doubles, weights preloaded as float2 pairs). MUFU.TANH activations.
__global__ void __launch_bounds__(32)
scan_kernel(const float4* __restrict__ xg,
            const float*  __restrict__ Whh,   // [64,16]
            float*        __restrict__ hout,  // [B,T,16]
            const int*    __restrict__ lengths,
            int apply_mask)
{
    const int lane = threadIdx.x;
    const int j    = lane & 15;
    const int b    = blockIdx.x * 2 + (lane >> 4);
    const bool odd = (j & 1);

    // packed weights along k: wX2[m] = (W_X[j][2m], W_X[j][2m+1])
    u64 wi2[8], wf2[8], wg2[8], wo2[8];
    {
        const float2* ri = (const float2*)(Whh + ( 0 + j) * 16);
        const float2* rf = (const float2*)(Whh + (16 + j) * 16);
        const float2* rg = (const float2*)(Whh + (32 + j) * 16);
        const float2* ro = (const float2*)(Whh + (48 + j) * 16);
#pragma unroll
        for (int m = 0; m < 8; ++m) {
            float2 vi = __ldg(ri + m), vf = __ldg(rf + m);
            float2 vg = __ldg(rg + m), vo = __ldg(ro + m);
            wi2[m] = pk2(vi.x, vi.y);
            wf2[m] = pk2(vf.x, vf.y);
            wg2[m] = pk2(vg.x, vg.y);
            wo2[m] = pk2(vo.x, vo.y);
        }
    }
    const int len = apply_mask ? lengths[b] : TT;

    const float4* xp = xg   + (size_t)b * TT * 16 + j;   // stride 16 float4 per t
    float*        hp = hout + (size_t)b * TT * 16 + j;

    float c = 0.0f, h = 0.0f;

    float4 buf[8];
#pragma unroll
    for (int u = 0; u < 8; ++u) buf[u] = xp[u * 16];

    for (int tb = 0; tb < TT; tb += 8) {
        float4 nb[8];
#pragma unroll
        for (int u = 0; u < 8; ++u) {
            int tn = tb + 8 + u; if (tn > TT - 1) tn = TT - 1;
            nb[u] = xp[tn * 16];
        }
#pragma unroll
        for (int u = 0; u < 8; ++u) {
            const int t = tb + u;
            const float4 cur = buf[u];

            // build packed h-pair (h_{2m}, h_{2m+1}) on every lane
            float e  = __shfl_xor_sync(0xffffffffu, h, 1);
            float lo = odd ? e : h;
            float hi = odd ? h : e;
            double h2d = __hiloint2double(__float_as_int(hi), __float_as_int(lo));

            u64 ai = 0ull, af = 0ull, ag = 0ull, ao = 0ull;
#pragma unroll
            for (int m = 0; m < 8; ++m) {
                double hm = __shfl_sync(0xffffffffu, h2d, m << 1, 16);
                u64 hu = (u64)__double_as_longlong(hm);
                ai = fma2(hu, wi2[m], ai);
                af = fma2(hu, wf2[m], af);
                ag = fma2(hu, wg2[m], ag);
                ao = fma2(hu, wo2[m], ao);
            }
            float l0, h0, l1, h1, l2, h2, l3, h3;
            upk2(l0, h0, ai); float a_i = cur.x + (l0 + h0);
            upk2(l1, h1, af); float a_f = cur.y + (l1 + h1);
            upk2(l2, h2, ag); float a_g = cur.z + (l2 + h2);
            upk2(l3, h3, ao); float a_o = cur.w + (l3 + h3);

            float gi = f_sigm(a_i);
            float gf = f_sigm(a_f);
            float gg = f_tanh(a_g);
            float go = f_sigm(a_o);
            c = fmaf(gf, c, gi * gg);
            h = go * f_tanh(c);

            hp[t * 16] = (t < len) ? h : 0.0f;
        }
#pragma unroll
        for (int u = 0; u < 8; ++u) buf[u] = nb[u];
    }
}

// ---------------- BN stats --------------------------------------------------
__global__ void zero_stats_kernel() {
    if (threadIdx.x < 32) g_stats[threadIdx.x] = 0.0f;
}

__global__ void stats_kernel(const float* __restrict__ h2)
{
    __shared__ float ss[16], sq[16];
    int tid = threadIdx.x;
    if (tid < 16) { ss[tid] = 0.0f; sq[tid] = 0.0f; }
    __syncthreads();
    int j = tid & 15;
    int rpb = blockDim.x >> 4;
    float s = 0.0f, s2 = 0.0f;
    for (int pos = blockIdx.x * rpb + (tid >> 4); pos < NPOS; pos += gridDim.x * rpb) {
        float v = h2[(size_t)pos * 16 + j];
        s += v; s2 += v * v;
    }
    atomicAdd(&ss[j], s);
    atomicAdd(&sq[j], s2);
    __syncthreads();
    if (tid < 16) {
        atomicAdd(&g_stats[tid],      ss[tid]);
        atomicAdd(&g_stats[16 + tid], sq[tid]);
    }
}

// ---------------- fold BN into FC ------------------------------------------
__global__ void coef_kernel(const float* __restrict__ gamma,
                            const float* __restrict__ beta,
                            const float* __restrict__ fcw,
                            const float* __restrict__ fcb)
{
    __shared__ float scl[16], sht[16];
    int tid = threadIdx.x;
    if (tid < 16) {
        const float inv_n = 1.0f / (float)NPOS;
        float mean = g_stats[tid] * inv_n;
        float var  = g_stats[16 + tid] * inv_n - mean * mean;
        float s = rsqrtf(var + 1e-5f) * gamma[tid];
        scl[tid] = s;
        sht[tid] = beta[tid] - mean * s;
    }
    __syncthreads();
    if (tid < 64) {
        int o = tid >> 4, jj = tid & 15;
        g_coef[tid] = fcw[o * 16 + jj] * scl[jj];
    }
    if (tid < 4) {
        float bb = fcb[tid];
        for (int jj = 0; jj < 16; ++jj)
            bb += fcw[tid * 16 + jj] * sht[jj];
        g_coef[64 + tid] = bb;
    }
}

// ---------------- final GEMV ------------------------------------------------
__global__ void out_kernel(const float* __restrict__ h2, float* __restrict__ out)
{
    int pos = blockIdx.x * blockDim.x + threadIdx.x;
    if (pos >= NPOS) return;
    const float4* hp = (const float4*)(h2 + (size_t)pos * 16);
    float4 v0 = hp[0], v1 = hp[1], v2 = hp[2], v3 = hp[3];
    float hv[16] = { v0.x, v0.y, v0.z, v0.w, v1.x, v1.y, v1.z, v1.w,
                     v2.x, v2.y, v2.z, v2.w, v3.x, v3.y, v3.z, v3.w };
    float o0 = g_coef[64], o1 = g_coef[65], o2 = g_coef[66], o3 = g_coef[67];
#pragma unroll
    for (int jj = 0; jj < 16; ++jj) {
        float hvv = hv[jj];
        o0 = fmaf(hvv, g_coef[ 0 + jj], o0);
        o1 = fmaf(hvv, g_coef[16 + jj], o1);
        o2 = fmaf(hvv, g_coef[32 + jj], o2);
        o3 = fmaf(hvv, g_coef[48 + jj], o3);
    }
    float4 r = { o0, o1, o2, o3 };
    ((float4*)out)[pos] = r;
}

// ---------------- host ------------------------------------------------------
extern "C" void kernel_launch(void* const* d_in, const int* in_sizes, int n_in,
                              void* d_out, int out_size)
{
    const float* x    = (const float*)d_in[0];
    const int*   len  = (const int*)  d_in[1];
    const float* Wih0 = (const float*)d_in[2];
    const float* Whh0 = (const float*)d_in[3];
    const float* bih0 = (const float*)d_in[4];
    const float* bhh0 = (const float*)d_in[5];
    const float* Wih1 = (const float*)d_in[6];
    const float* Whh1 = (const float*)d_in[7];
    const float* bih1 = (const float*)d_in[8];
    const float* bhh1 = (const float*)d_in[9];
    const float* Wih2 = (const float*)d_in[10];
    const float* Whh2 = (const float*)d_in[11];
    const float* bih2 = (const float*)d_in[12];
    const float* bhh2 = (const float*)d_in[13];
    const float* gam  = (const float*)d_in[14];
    const float* bet  = (const float*)d_in[15];
    const float* fcw  = (const float*)d_in[16];
    const float* fcb  = (const float*)d_in[17];

    float *xg, *ha, *hb;
    cudaGetSymbolAddress((void**)&xg, g_xg);
    cudaGetSymbolAddress((void**)&ha, g_ha);
    cudaGetSymbolAddress((void**)&hb, g_hb);

    constexpr int PPB = 64;
    const int proj_grid = NPOS / PPB;   // 8192

    // layer 0
    proj_kernel<DD0, PPB><<<proj_grid, 256>>>(x, Wih0, bih0, bhh0, xg);
    scan_kernel<<<BB / 2, 32>>>((const float4*)xg, Whh0, ha, len, 0);
    // layer 1
    proj_kernel<HH, PPB><<<proj_grid, 256>>>(ha, Wih1, bih1, bhh1, xg);
    scan_kernel<<<BB / 2, 32>>>((const float4*)xg, Whh1, hb, len, 0);
    // layer 2 (mask applied at store)
    proj_kernel<HH, PPB><<<proj_grid, 256>>>(hb, Wih2, bih2, bhh2, xg);
    scan_kernel<<<BB / 2, 32>>>((const float4*)xg, Whh2, ha, len, 1);

    // BN stats + fold into FC + output
    zero_stats_kernel<<<1, 32>>>();
    stats_kernel<<<1024, 256>>>(ha);
    coef_kernel<<<1, 64>>>(gam, bet, fcw, fcb);
    out_kernel<<<NPOS / 256, 256>>>(ha, (float*)d_out);
}